// round 14
// baseline (speedup 1.0000x reference)
#include <cuda_runtime.h>
#include <cstdint>

#define ROWS_TOTAL 32768
#define DIM 768
#define NF 16
#define NQ 8

/* ---- kernel 1 : eighth-K GEMM, RPT=4, x direct from global ---- */
#define BLOCK 128
#define RPT 4
#define ROWS_PB 512
#define NSPLIT 8
#define KE 96                         /* K eighth per block */
#define WE_FLOATS (KE * NF)           /* 1536 floats = 6KB */
#define NGROUPS (ROWS_TOTAL / ROWS_PB)

__device__ float g_part[NSPLIT][ROWS_TOTAL * NF];   /* 16MB scratch */

__device__ __forceinline__ void ffma2(unsigned long long &d,
                                      unsigned long long a,
                                      unsigned long long b) {
    asm("fma.rn.f32x2 %0, %1, %2, %0;" : "+l"(d) : "l"(a), "l"(b));
}

__device__ __forceinline__ unsigned long long splat(float v) {
    unsigned long long r;
    asm("mov.b64 %0, {%1, %1};" : "=l"(r) : "f"(v));
    return r;
}

__global__ __launch_bounds__(BLOCK, 4)
void qadapter_gemm(const float* __restrict__ x,
                   const float* __restrict__ W) {
    __shared__ float W_s[WE_FLOATS];

    const int tid  = threadIdx.x;
    const int e    = blockIdx.x & 7;
    const int base = (blockIdx.x >> 3) * ROWS_PB;

    /* one-time W stage: 384 float4, 3 per thread */
    {
        const float4* Wsrc = reinterpret_cast<const float4*>(W + e * KE * NF);
        #pragma unroll
        for (int i = 0; i < 3; i++) {
            int g4 = i * BLOCK + tid;
            reinterpret_cast<float4*>(W_s)[g4] = Wsrc[g4];
        }
    }
    __syncthreads();

    /* per-thread row pointers (rows tid + 128j), offset to this K eighth */
    const float4* xr[RPT];
    #pragma unroll
    for (int j = 0; j < RPT; j++)
        xr[j] = reinterpret_cast<const float4*>(
            x + (size_t)(base + tid + j * BLOCK) * DIM + e * KE);

    unsigned long long acc[RPT][8];
    #pragma unroll
    for (int j = 0; j < RPT; j++)
        #pragma unroll
        for (int i = 0; i < 8; i++) acc[j][i] = 0ull;

    #pragma unroll 4
    for (int kg = 0; kg < KE / 4; kg++) {      /* 24 k-groups of 4 */
        float4 xv[RPT];
        #pragma unroll
        for (int j = 0; j < RPT; j++)
            xv[j] = xr[j][kg];                 /* LDG.128, line-sequential */
        const float xe[RPT][4] = {
            {xv[0].x, xv[0].y, xv[0].z, xv[0].w},
            {xv[1].x, xv[1].y, xv[1].z, xv[1].w},
            {xv[2].x, xv[2].y, xv[2].z, xv[2].w},
            {xv[3].x, xv[3].y, xv[3].z, xv[3].w}};
        const float* wc = W_s + kg * 4 * NF;
        #pragma unroll
        for (int kj = 0; kj < 4; kj++) {
            const ulonglong2* wp =
                reinterpret_cast<const ulonglong2*>(wc + kj * NF);
            ulonglong2 w01 = wp[0];            /* full-warp broadcast LDS.128 */
            ulonglong2 w23 = wp[1];
            ulonglong2 w45 = wp[2];
            ulonglong2 w67 = wp[3];
            #pragma unroll
            for (int j = 0; j < RPT; j++) {
                unsigned long long xs = splat(xe[j][kj]);
                ffma2(acc[j][0], xs, w01.x);
                ffma2(acc[j][1], xs, w01.y);
                ffma2(acc[j][2], xs, w23.x);
                ffma2(acc[j][3], xs, w23.y);
                ffma2(acc[j][4], xs, w45.x);
                ffma2(acc[j][5], xs, w45.y);
                ffma2(acc[j][6], xs, w67.x);
                ffma2(acc[j][7], xs, w67.y);
            }
        }
    }

    /* write fp32 partials for 4 rows */
    #pragma unroll
    for (int j = 0; j < RPT; j++) {
        float4* dst = reinterpret_cast<float4*>(
            &g_part[e][(size_t)(base + tid + j * BLOCK) * NF]);
        #pragma unroll
        for (int i = 0; i < 4; i++) {
            float a  = __uint_as_float((unsigned int)(acc[j][2 * i] & 0xffffffffull));
            float bb = __uint_as_float((unsigned int)(acc[j][2 * i] >> 32));
            float c  = __uint_as_float((unsigned int)(acc[j][2 * i + 1] & 0xffffffffull));
            float d  = __uint_as_float((unsigned int)(acc[j][2 * i + 1] >> 32));
            dst[i] = make_float4(a, bb, c, d);
        }
    }
}

/* ---- kernel 2 : combine 8 partials, 8 threads/row (1 qubit each) ---- */
__global__ __launch_bounds__(256)
void qadapter_epi(const float* __restrict__ b,
                  const float* __restrict__ enc,
                  float* __restrict__ out) {
    const int idx = blockIdx.x * 256 + threadIdx.x;   /* 262144 total */
    const int row = idx >> 3;
    const int q   = idx & 7;                          /* qubit = col pair 2q */
    const size_t off = (size_t)row * NF + 2 * q;

    float sx = 0.0f, sy = 0.0f;
    #pragma unroll
    for (int e = 0; e < NSPLIT; e++) {
        float2 p = *reinterpret_cast<const float2*>(&g_part[e][off]);
        sx += p.x;
        sy += p.y;
    }
    float z0 = sx + __ldg(&b[2 * q]);
    float z1 = sy + __ldg(&b[2 * q + 1]);
    float e0 = __expf(2.0f * z0), e1 = __expf(2.0f * z1);
    float t0 = __fdividef(e0 - 1.0f, e0 + 1.0f);
    float t1 = __fdividef(e1 - 1.0f, e1 + 1.0f);
    float theta = t0 + __ldg(&enc[q * 3 + 0]);
    float phi   = t1 + __ldg(&enc[q * 3 + 1]);
    float sn, cs;
    __sincosf(0.5f * theta, &sn, &cs);
    *reinterpret_cast<float2*>(out + off) = make_float2(cs, sn * __cosf(phi));
}

extern "C" void kernel_launch(void* const* d_in, const int* in_sizes, int n_in,
                              void* d_out, int out_size) {
    const float* x   = (const float*)d_in[0];
    const float* W   = (const float*)d_in[1];
    const float* b   = (const float*)d_in[2];
    const float* enc = (const float*)d_in[3];
    float* out = (float*)d_out;

    qadapter_gemm<<<NGROUPS * NSPLIT, BLOCK>>>(x, W);
    qadapter_epi<<<(ROWS_TOTAL * 8) / 256, 256>>>(b, enc, out);
}

// round 16
// speedup vs baseline: 1.1144x; 1.1144x over previous
#include <cuda_runtime.h>
#include <cstdint>

#define ROWS_TOTAL 32768
#define DIM 768
#define NF 16
#define NQ 8

#define BLOCK 128
#define RPT 4
#define ROWS_PB 512
#define NSPLIT 4
#define KQ 192                        /* K quarter per block */
#define KB 16                         /* k per chunk (R8-proven) */
#define NCHUNK (KQ / KB)              /* 12 */
#define LDX 20                        /* 16 + 4 pad, conflict-free (R8) */
#define WQ_FLOATS (KQ * NF)           /* 3072 = 12KB */
#define XBUF_FLOATS (ROWS_PB * LDX)   /* 10240 = 40KB */
#define SMEM_BYTES ((WQ_FLOATS + 2 * XBUF_FLOATS) * 4)  /* 94208 -> 2/SM */
#define NGROUPS (ROWS_TOTAL / ROWS_PB)  /* 64 */

__device__ float g_part[NSPLIT][ROWS_TOTAL * NF];   /* 8MB scratch */
__device__ unsigned g_ctr[NGROUPS];                  /* zero-init; stays ==0 mod 4 */

__device__ __forceinline__ void ffma2(unsigned long long &d,
                                      unsigned long long a,
                                      unsigned long long b) {
    asm("fma.rn.f32x2 %0, %1, %2, %0;" : "+l"(d) : "l"(a), "l"(b));
}

__device__ __forceinline__ unsigned long long splat(float v) {
    unsigned long long r;
    asm("mov.b64 %0, {%1, %1};" : "=l"(r) : "f"(v));
    return r;
}

__device__ __forceinline__ void cp_async16(float* dst, const float* src) {
    unsigned int d = (unsigned int)__cvta_generic_to_shared(dst);
    asm volatile("cp.async.cg.shared.global [%0], [%1], 16;" :: "r"(d), "l"(src));
}

/* stage one 512-row x 16-k chunk: 2048 float4, 16 per thread (R8 layout) */
__device__ __forceinline__ void stage_x(const float* __restrict__ xq,
                                        float* __restrict__ dst,
                                        int c, int tid) {
    const float* src = xq + c * KB;
    #pragma unroll
    for (int i = 0; i < 16; i++) {
        int pos = i * BLOCK + tid;
        int row = pos >> 2, c4 = (pos & 3) << 2;
        cp_async16(dst + row * LDX + c4, src + (size_t)row * DIM + c4);
    }
    asm volatile("cp.async.commit_group;");
}

/* ---- epilogue for one rowgroup: kept OUT of the mainloop's register
   allocation via noinline. Reads partials through L2 (__ldcg). ---- */
__device__ __noinline__ void epilogue_rowgroup(int base, int tid,
                                               const float* __restrict__ b,
                                               const float* __restrict__ enc,
                                               float* __restrict__ out) {
    for (int j = 0; j < RPT; j++) {
        const size_t row = (size_t)(base + tid + j * BLOCK);
        float s[16];
        #pragma unroll
        for (int i = 0; i < 4; i++) {
            float4 a0 = __ldcg(reinterpret_cast<const float4*>(&g_part[0][row * NF + 4 * i]));
            float4 a1 = __ldcg(reinterpret_cast<const float4*>(&g_part[1][row * NF + 4 * i]));
            float4 a2 = __ldcg(reinterpret_cast<const float4*>(&g_part[2][row * NF + 4 * i]));
            float4 a3 = __ldcg(reinterpret_cast<const float4*>(&g_part[3][row * NF + 4 * i]));
            float z0 = (a0.x + a1.x) + (a2.x + a3.x) + __ldg(&b[4 * i]);
            float z1 = (a0.y + a1.y) + (a2.y + a3.y) + __ldg(&b[4 * i + 1]);
            float z2 = (a0.z + a1.z) + (a2.z + a3.z) + __ldg(&b[4 * i + 2]);
            float z3 = (a0.w + a1.w) + (a2.w + a3.w) + __ldg(&b[4 * i + 3]);
            float e0 = __expf(2.0f * z0), e1 = __expf(2.0f * z1);
            float e2 = __expf(2.0f * z2), e3 = __expf(2.0f * z3);
            s[4 * i]     = __fdividef(e0 - 1.0f, e0 + 1.0f);
            s[4 * i + 1] = __fdividef(e1 - 1.0f, e1 + 1.0f);
            s[4 * i + 2] = __fdividef(e2 - 1.0f, e2 + 1.0f);
            s[4 * i + 3] = __fdividef(e3 - 1.0f, e3 + 1.0f);
        }
        float o[16];
        #pragma unroll
        for (int q = 0; q < NQ; q++) {
            float theta = s[2 * q]     + __ldg(&enc[q * 3 + 0]);
            float phi   = s[2 * q + 1] + __ldg(&enc[q * 3 + 1]);
            float sn, cs;
            __sincosf(0.5f * theta, &sn, &cs);
            o[2 * q]     = cs;
            o[2 * q + 1] = sn * __cosf(phi);
        }
        float4* op = reinterpret_cast<float4*>(out + row * NF);
        #pragma unroll
        for (int i = 0; i < 4; i++)
            op[i] = make_float4(o[4 * i], o[4 * i + 1], o[4 * i + 2], o[4 * i + 3]);
    }
}

__global__ __launch_bounds__(BLOCK, 2)
void qadapter_kernel(const float* __restrict__ x,
                     const float* __restrict__ W,
                     const float* __restrict__ b,
                     const float* __restrict__ enc,
                     float* __restrict__ out) {
    extern __shared__ float smem[];
    float* W_s = smem;                 /* 3072 floats */
    float* x_s = smem + WQ_FLOATS;     /* 2 x 10240 floats */
    __shared__ unsigned s_last;

    const int tid     = threadIdx.x;
    const int quarter = blockIdx.x & 3;
    const int grp     = blockIdx.x >> 2;
    const int base    = grp * ROWS_PB;
    const float* xq   = x + (size_t)base * DIM + quarter * KQ;

    /* stage W quarter : group 0 (768 float4, 6 per thread) */
    {
        const float4* Wsrc =
            reinterpret_cast<const float4*>(W + quarter * KQ * NF);
        #pragma unroll
        for (int i = 0; i < 6; i++) {
            int g4 = i * BLOCK + tid;
            cp_async16(W_s + g4 * 4, reinterpret_cast<const float*>(Wsrc + g4));
        }
        asm volatile("cp.async.commit_group;");
    }
    stage_x(xq, x_s, 0, tid);                 /* group 1 */
    stage_x(xq, x_s + XBUF_FLOATS, 1, tid);   /* group 2 */

    unsigned long long acc[RPT][8];
    #pragma unroll
    for (int j = 0; j < RPT; j++)
        #pragma unroll
        for (int i = 0; i < 8; i++) acc[j][i] = 0ull;

    for (int ch = 0; ch < NCHUNK; ch++) {
        if (ch < NCHUNK - 1) asm volatile("cp.async.wait_group 1;");
        else                 asm volatile("cp.async.wait_group 0;");
        __syncthreads();

        const float* xr = x_s + (ch & 1) * XBUF_FLOATS + tid * LDX;
        const float* wc = W_s + ch * (KB * NF);

        #pragma unroll
        for (int kk = 0; kk < KB; kk += 4) {
            float4 xv[RPT];
            #pragma unroll
            for (int j = 0; j < RPT; j++)
                xv[j] = *reinterpret_cast<const float4*>(
                    xr + j * (BLOCK * LDX) + kk);
            const float xe[RPT][4] = {
                {xv[0].x, xv[0].y, xv[0].z, xv[0].w},
                {xv[1].x, xv[1].y, xv[1].z, xv[1].w},
                {xv[2].x, xv[2].y, xv[2].z, xv[2].w},
                {xv[3].x, xv[3].y, xv[3].z, xv[3].w}};
            #pragma unroll
            for (int kj = 0; kj < 4; kj++) {
                const ulonglong2* wp = reinterpret_cast<const ulonglong2*>(
                    wc + (kk + kj) * NF);
                ulonglong2 w01 = wp[0];   /* full-warp broadcast LDS.128 */
                ulonglong2 w23 = wp[1];
                ulonglong2 w45 = wp[2];
                ulonglong2 w67 = wp[3];
                #pragma unroll
                for (int j = 0; j < RPT; j++) {
                    unsigned long long xs = splat(xe[j][kj]);
                    ffma2(acc[j][0], xs, w01.x);
                    ffma2(acc[j][1], xs, w01.y);
                    ffma2(acc[j][2], xs, w23.x);
                    ffma2(acc[j][3], xs, w23.y);
                    ffma2(acc[j][4], xs, w45.x);
                    ffma2(acc[j][5], xs, w45.y);
                    ffma2(acc[j][6], xs, w67.x);
                    ffma2(acc[j][7], xs, w67.y);
                }
            }
        }
        __syncthreads();
        if (ch + 2 < NCHUNK)
            stage_x(xq, x_s + (ch & 1) * XBUF_FLOATS, ch + 2, tid);
    }

    /* write fp32 partials for 4 rows */
    #pragma unroll
    for (int j = 0; j < RPT; j++) {
        float4* dst = reinterpret_cast<float4*>(
            &g_part[quarter][(size_t)(base + tid + j * BLOCK) * NF]);
        #pragma unroll
        for (int i = 0; i < 4; i++) {
            float a  = __uint_as_float((unsigned int)(acc[j][2 * i] & 0xffffffffull));
            float bb = __uint_as_float((unsigned int)(acc[j][2 * i] >> 32));
            float c  = __uint_as_float((unsigned int)(acc[j][2 * i + 1] & 0xffffffffull));
            float d  = __uint_as_float((unsigned int)(acc[j][2 * i + 1] >> 32));
            dst[i] = make_float4(a, bb, c, d);
        }
    }

    /* release partials, elect last sibling block of this rowgroup */
    __threadfence();
    __syncthreads();
    if (tid == 0) {
        unsigned old = atomicAdd(&g_ctr[grp], 1u);
        s_last = ((old & 3u) == 3u) ? 1u : 0u;
    }
    __syncthreads();
    if (s_last)
        epilogue_rowgroup(base, tid, b, enc, out);
}

extern "C" void kernel_launch(void* const* d_in, const int* in_sizes, int n_in,
                              void* d_out, int out_size) {
    const float* x   = (const float*)d_in[0];
    const float* W   = (const float*)d_in[1];
    const float* b   = (const float*)d_in[2];
    const float* enc = (const float*)d_in[3];
    float* out = (float*)d_out;

    cudaFuncSetAttribute(qadapter_kernel,
                         cudaFuncAttributeMaxDynamicSharedMemorySize, SMEM_BYTES);
    qadapter_kernel<<<NGROUPS * NSPLIT, BLOCK, SMEM_BYTES>>>(x, W, b, enc, out);
}

// round 17
// speedup vs baseline: 1.4177x; 1.2721x over previous
#include <cuda_runtime.h>
#include <cstdint>

#define ROWS_TOTAL 32768
#define DIM 768
#define NF 16
#define NQ 8

/* ---------- kernel 1 : quarter-K GEMM, 4 rows per thread (R8 verbatim) ---------- */
#define BLOCK 128
#define RPT 4                        /* rows per thread */
#define ROWS_PB (BLOCK * RPT)        /* 512 */
#define KQ 192                       /* K quarter */
#define KB 16                        /* k per chunk */
#define LDX 20                       /* row stride in x smem (conflict-free) */
#define NCHUNK (KQ / KB)             /* 12 */
#define WQ_FLOATS (KQ * NF)          /* 3072 floats = 12KB */
#define XS_FLOATS (ROWS_PB * LDX)    /* 10240 */
#define SMEM_BYTES ((WQ_FLOATS + 2 * XS_FLOATS) * 4)  /* 94208 B -> 2 blocks/SM */

__device__ float g_part[4][ROWS_TOTAL * NF];   /* 8MB scratch */

__device__ __forceinline__ void ffma2(unsigned long long &d,
                                      unsigned long long a,
                                      unsigned long long b) {
    asm("fma.rn.f32x2 %0, %1, %2, %0;" : "+l"(d) : "l"(a), "l"(b));
}

__device__ __forceinline__ unsigned long long splat(float v) {
    unsigned long long r;
    asm("mov.b64 %0, {%1, %1};" : "=l"(r) : "f"(v));
    return r;
}

__device__ __forceinline__ void cp_async16(float* dst, const float* src) {
    unsigned int d = (unsigned int)__cvta_generic_to_shared(dst);
    asm volatile("cp.async.cg.shared.global [%0], [%1], 16;" :: "r"(d), "l"(src));
}

/* stage one 512-row x 16-k chunk: 2048 float4, 16 per thread */
__device__ __forceinline__ void stage_x(const float* __restrict__ xq,
                                        float* __restrict__ dst,
                                        int ch, int tid) {
    const float* src = xq + ch * KB;
    #pragma unroll
    for (int i = 0; i < 16; i++) {
        int pos = i * BLOCK + tid;
        int row = pos >> 2, c4 = (pos & 3) << 2;
        cp_async16(dst + row * LDX + c4, src + (size_t)row * DIM + c4);
    }
    asm volatile("cp.async.commit_group;");
}

__global__ __launch_bounds__(BLOCK)
void qadapter_gemm(const float* __restrict__ x,
                   const float* __restrict__ W) {
    extern __shared__ float smem[];
    float* W_s = smem;                 /* 3072 floats */
    float* x_s = smem + WQ_FLOATS;     /* 2 x 10240 floats */

    const int tid     = threadIdx.x;
    const int quarter = blockIdx.x & 3;
    const int base    = (blockIdx.x >> 2) * ROWS_PB;
    const float* xq   = x + (size_t)base * DIM + quarter * KQ;

    /* stage this quarter's W : group 0 (768 float4 / 128 thr = 6 each) */
    {
        const float4* Wsrc =
            reinterpret_cast<const float4*>(W + quarter * KQ * NF);
        #pragma unroll
        for (int i = 0; i < 6; i++) {
            int g4 = i * BLOCK + tid;
            cp_async16(W_s + g4 * 4, reinterpret_cast<const float*>(Wsrc + g4));
        }
        asm volatile("cp.async.commit_group;");
    }
    stage_x(xq, x_s, 0, tid);                 /* group 1 */
    stage_x(xq, x_s + XS_FLOATS, 1, tid);     /* group 2 */

    unsigned long long acc[RPT][8];    /* [row][col-pair] */
    #pragma unroll
    for (int j = 0; j < RPT; j++)
        #pragma unroll
        for (int i = 0; i < 8; i++) acc[j][i] = 0ull;

    for (int ch = 0; ch < NCHUNK; ch++) {
        if (ch < NCHUNK - 1) asm volatile("cp.async.wait_group 1;");
        else                 asm volatile("cp.async.wait_group 0;");
        __syncthreads();

        const float* xb = x_s + (ch & 1) * XS_FLOATS + tid * LDX;
        const float* wc = W_s + ch * (KB * NF);

        #pragma unroll
        for (int kk = 0; kk < KB; kk += 4) {
            float4 xv[RPT];
            #pragma unroll
            for (int j = 0; j < RPT; j++)
                xv[j] = *reinterpret_cast<const float4*>(
                    xb + j * (BLOCK * LDX) + kk);
            const float xe[RPT][4] = {
                {xv[0].x, xv[0].y, xv[0].z, xv[0].w},
                {xv[1].x, xv[1].y, xv[1].z, xv[1].w},
                {xv[2].x, xv[2].y, xv[2].z, xv[2].w},
                {xv[3].x, xv[3].y, xv[3].z, xv[3].w}};
            #pragma unroll
            for (int kj = 0; kj < 4; kj++) {
                const ulonglong2* wp = reinterpret_cast<const ulonglong2*>(
                    wc + (kk + kj) * NF);
                ulonglong2 w01 = wp[0];   /* full-warp broadcast LDS.128 */
                ulonglong2 w23 = wp[1];
                ulonglong2 w45 = wp[2];
                ulonglong2 w67 = wp[3];
                #pragma unroll
                for (int j = 0; j < RPT; j++) {
                    unsigned long long xs = splat(xe[j][kj]);
                    ffma2(acc[j][0], xs, w01.x);
                    ffma2(acc[j][1], xs, w01.y);
                    ffma2(acc[j][2], xs, w23.x);
                    ffma2(acc[j][3], xs, w23.y);
                    ffma2(acc[j][4], xs, w45.x);
                    ffma2(acc[j][5], xs, w45.y);
                    ffma2(acc[j][6], xs, w67.x);
                    ffma2(acc[j][7], xs, w67.y);
                }
            }
        }
        __syncthreads();
        if (ch + 2 < NCHUNK)
            stage_x(xq, x_s + (ch & 1) * XS_FLOATS, ch + 2, tid);
    }

    /* write fp32 partials for 4 rows */
    #pragma unroll
    for (int j = 0; j < RPT; j++) {
        float4* dst = reinterpret_cast<float4*>(
            &g_part[quarter][(size_t)(base + tid + j * BLOCK) * NF]);
        #pragma unroll
        for (int i = 0; i < 4; i++) {
            float a  = __uint_as_float((unsigned int)(acc[j][2 * i] & 0xffffffffull));
            float bb = __uint_as_float((unsigned int)(acc[j][2 * i] >> 32));
            float c  = __uint_as_float((unsigned int)(acc[j][2 * i + 1] & 0xffffffffull));
            float d  = __uint_as_float((unsigned int)(acc[j][2 * i + 1] >> 32));
            dst[i] = make_float4(a, bb, c, d);
        }
    }
}

/* ---------- kernel 2 : combine 4 partials, 4 threads/row (R13 verbatim) ---------- */
__global__ __launch_bounds__(256)
void qadapter_epi(const float* __restrict__ b,
                  const float* __restrict__ enc,
                  float* __restrict__ out) {
    const int idx = blockIdx.x * 256 + threadIdx.x;   /* 131072 total */
    const int row = idx >> 2;
    const int cg  = idx & 3;
    const size_t off = (size_t)row * NF + cg * 4;

    float4 p0 = *reinterpret_cast<const float4*>(&g_part[0][off]);
    float4 p1 = *reinterpret_cast<const float4*>(&g_part[1][off]);
    float4 p2 = *reinterpret_cast<const float4*>(&g_part[2][off]);
    float4 p3 = *reinterpret_cast<const float4*>(&g_part[3][off]);

    float z0 = (p0.x + p1.x) + (p2.x + p3.x) + __ldg(&b[4 * cg]);
    float z1 = (p0.y + p1.y) + (p2.y + p3.y) + __ldg(&b[4 * cg + 1]);
    float z2 = (p0.z + p1.z) + (p2.z + p3.z) + __ldg(&b[4 * cg + 2]);
    float z3 = (p0.w + p1.w) + (p2.w + p3.w) + __ldg(&b[4 * cg + 3]);
    float e0 = __expf(2.0f * z0), e1 = __expf(2.0f * z1);
    float e2 = __expf(2.0f * z2), e3 = __expf(2.0f * z3);
    float t0 = __fdividef(e0 - 1.0f, e0 + 1.0f);
    float t1 = __fdividef(e1 - 1.0f, e1 + 1.0f);
    float t2 = __fdividef(e2 - 1.0f, e2 + 1.0f);
    float t3 = __fdividef(e3 - 1.0f, e3 + 1.0f);

    int q0 = 2 * cg, q1 = 2 * cg + 1;
    float th0 = t0 + __ldg(&enc[q0 * 3 + 0]);
    float ph0 = t1 + __ldg(&enc[q0 * 3 + 1]);
    float th1 = t2 + __ldg(&enc[q1 * 3 + 0]);
    float ph1 = t3 + __ldg(&enc[q1 * 3 + 1]);
    float sn0, cs0, sn1, cs1;
    __sincosf(0.5f * th0, &sn0, &cs0);
    __sincosf(0.5f * th1, &sn1, &cs1);
    *reinterpret_cast<float4*>(out + off) =
        make_float4(cs0, sn0 * __cosf(ph0), cs1, sn1 * __cosf(ph1));
}

extern "C" void kernel_launch(void* const* d_in, const int* in_sizes, int n_in,
                              void* d_out, int out_size) {
    const float* x   = (const float*)d_in[0];
    const float* W   = (const float*)d_in[1];
    const float* b   = (const float*)d_in[2];
    const float* enc = (const float*)d_in[3];
    float* out = (float*)d_out;

    cudaFuncSetAttribute(qadapter_gemm,
                         cudaFuncAttributeMaxDynamicSharedMemorySize, SMEM_BYTES);
    qadapter_gemm<<<(ROWS_TOTAL / ROWS_PB) * 4, BLOCK, SMEM_BYTES>>>(x, W);
    qadapter_epi<<<(ROWS_TOTAL * 4) / 256, 256>>>(b, enc, out);
}